// round 15
// baseline (speedup 1.0000x reference)
#include <cuda_runtime.h>
#include <cstdint>

#define BLOCK 128
#define MTILE 32
#define MM 16
#define NMAX 8192
#define CHUNK 128
#define HALF_LN2 0.34657359027997264f
#define EPS_S 1e-5f

typedef unsigned long long ull;

// prologue-packed operands
// g_yp: per j-pair p (j0=2p, j1=2p+1): [2p]   = (x0, x1, y0, y1)
//                                      [2p+1] = (z0, z1, w0+eps, w1+eps)  (w=|y|^2)
__device__ float4 g_yp[NMAX];
// g_bf: fragment-major B. Per 8-pair block gb, lane l (t4=l&3, g=l>>2), word w:
//   w0=(pair t4,  col g) w1=(pair t4+4, col g) w2=(pair t4, col g+8) w3=(pair t4+4, col g+8)
//   each word = f16x2(0.5*ln2*coeff[2p][c], 0.5*ln2*coeff[2p+1][c])
__device__ uint32_t g_bf[(NMAX / 16) * 128];

__device__ __forceinline__ uint32_t pack_f16x2(float lo, float hi) {
    uint32_t d;
    asm("cvt.rn.f16x2.f32 %0, %1, %2;" : "=r"(d) : "f"(hi), "f"(lo));
    return d;
}

// ---- packed f32x2 helpers (Blackwell FFMA2 path) ----
__device__ __forceinline__ ull fma2(ull a, ull b, ull c) {
    ull d;
    asm("fma.rn.f32x2 %0, %1, %2, %3;" : "=l"(d) : "l"(a), "l"(b), "l"(c));
    return d;
}
__device__ __forceinline__ ull add2(ull a, ull b) {
    ull d;
    asm("add.rn.f32x2 %0, %1, %2;" : "=l"(d) : "l"(a), "l"(b));
    return d;
}
__device__ __forceinline__ ull dup2(float v) {
    ull d;
    uint32_t b = __float_as_uint(v);
    asm("mov.b64 %0, {%1, %2};" : "=l"(d) : "r"(b), "r"(b));
    return d;
}
__device__ __forceinline__ float2 unpk(ull p) {
    uint32_t lo, hi;
    asm("mov.b64 {%0, %1}, %2;" : "=r"(lo), "=r"(hi) : "l"(p));
    return make_float2(__uint_as_float(lo), __uint_as_float(hi));
}

struct XP { ull x, y, z, w; };   // duplicated (v,v) per component; w = |x|^2

// phi for a j-pair against one x row, returned as f16x2 A-fragment word.
// s = |x|^2 + (-2x.y) + |y|^2+eps > 0 guaranteed (eps dominates fp32 rounding).
__device__ __forceinline__ uint32_t phi2pack(const XP& X, ulonglong2 a, ulonglong2 b) {
    ull c0 = add2(b.y, X.w);
    ull c1 = fma2(X.z, b.x, c0);
    ull c2 = fma2(X.y, a.y, c1);
    ull s  = fma2(X.x, a.x, c2);
    float2 sf = unpk(s);
    float p0 = sf.x * __log2f(sf.x);
    float p1 = sf.y * __log2f(sf.y);
    return pack_f16x2(p0, p1);
}

__device__ __forceinline__ void mma_f16(float* c, const uint32_t* a, uint32_t b0, uint32_t b1) {
    asm volatile(
        "mma.sync.aligned.m16n8k16.row.col.f32.f16.f16.f32 "
        "{%0,%1,%2,%3}, {%4,%5,%6,%7}, {%8,%9}, {%0,%1,%2,%3};"
        : "+f"(c[0]), "+f"(c[1]), "+f"(c[2]), "+f"(c[3])
        : "r"(a[0]), "r"(a[1]), "r"(a[2]), "r"(a[3]), "r"(b0), "r"(b1));
}

__device__ __forceinline__ uint32_t smem_u32(const void* p) {
    uint32_t a;
    asm("{ .reg .u64 t; cvta.to.shared.u64 t, %1; cvt.u32.u64 %0, t; }" : "=r"(a) : "l"(p));
    return a;
}

#define CP16(dst_u32, src_ptr) \
    asm volatile("cp.async.cg.shared.global [%0], [%1], 16;" :: "r"(dst_u32), "l"(src_ptr))

// ---------------- prologue ----------------
__global__ void prep_kernel(const float* __restrict__ y,
                            const float* __restrict__ coeffs,
                            int n, int npad) {
    int i = blockIdx.x * blockDim.x + threadIdx.x;
    int npairs = npad >> 1;
    if (i < npairs) {
        int j0 = 2 * i, j1 = 2 * i + 1;
        float a0 = 0.f, b0 = 0.f, c0 = 0.f, w0 = 1.f;
        float a1 = 0.f, b1 = 0.f, c1 = 0.f, w1 = 1.f;
        if (j0 < n) {
            a0 = y[3 * j0]; b0 = y[3 * j0 + 1]; c0 = y[3 * j0 + 2];
            w0 = fmaf(a0, a0, fmaf(b0, b0, c0 * c0)) + EPS_S;
            a0 = -2.f * a0; b0 = -2.f * b0; c0 = -2.f * c0;
        }
        if (j1 < n) {
            a1 = y[3 * j1]; b1 = y[3 * j1 + 1]; c1 = y[3 * j1 + 2];
            w1 = fmaf(a1, a1, fmaf(b1, b1, c1 * c1)) + EPS_S;
            a1 = -2.f * a1; b1 = -2.f * b1; c1 = -2.f * c1;
        }
        g_yp[2 * i + 0] = make_float4(a0, a1, b0, b1);
        g_yp[2 * i + 1] = make_float4(c0, c1, w0, w1);
    }
    // fragment-major B: i over (npad/16 blocks) * 128 words
    int npe = (npad >> 4) * 128;
    if (i < npe) {
        int gb = i >> 7;            // 8-pair block
        int l  = (i >> 2) & 31;     // lane
        int wd = i & 3;             // word
        int t4 = l & 3, g = l >> 2;
        int pl  = t4 + (wd & 1) * 4;        // pair within block
        int col = g + (wd >> 1) * 8;        // output column
        int p   = gb * 8 + pl;              // global pair
        int j0 = 2 * p, j1 = 2 * p + 1;
        float f0 = (j0 < n) ? HALF_LN2 * coeffs[(size_t)j0 * MM + col] : 0.f;
        float f1 = (j1 < n) ? HALF_LN2 * coeffs[(size_t)j1 * MM + col] : 0.f;
        g_bf[i] = pack_f16x2(f0, f1);
    }
}

// ---------------- main kernel ----------------
__global__ __launch_bounds__(BLOCK, 6) void rbf_tps_mma_kernel(
    const float* __restrict__ x,
    const float* __restrict__ shift,
    const float* __restrict__ scale,
    const float* __restrict__ coeffs,
    const int*   __restrict__ powers,
    float* __restrict__ out,
    int nx, int n, int npad, int r)
{
    __shared__ __align__(16) ulonglong2 sv[2][CHUNK];   // 4 KB: 64 pairs x 2 entries per buf
    __shared__ __align__(16) uint32_t sbf[2][1024];     // 8 KB fragment-major B
    __shared__ float sred[3][32][MM];                   // 6 KB

    const int tid  = threadIdx.x;
    const int lane = tid & 31;
    const int w    = tid >> 5;
    const int t4   = lane & 3;
    const int g    = lane >> 2;

    const int tilebase = blockIdx.x * MTILE;

    // duplicated x operands for rows g, g+8, g+16, g+24
    XP Xd[4];
#pragma unroll
    for (int i = 0; i < 4; ++i) {
        int row = tilebase + g + 8 * i;
        float xx = 0.f, xy = 0.f, xz = 0.f;
        if (row < nx) {
            xx = x[3 * row + 0];
            xy = x[3 * row + 1];
            xz = x[3 * row + 2];
        }
        float x2 = fmaf(xx, xx, fmaf(xy, xy, xz * xz));
        Xd[i].x = dup2(xx);
        Xd[i].y = dup2(xy);
        Xd[i].z = dup2(xz);
        Xd[i].w = dup2(x2);
    }

    float acc[2][2][4];
#pragma unroll
    for (int a = 0; a < 2; ++a)
#pragma unroll
        for (int b = 0; b < 2; ++b)
#pragma unroll
            for (int c = 0; c < 4; ++c) acc[a][b][c] = 0.f;

    const int nchunks = npad / CHUNK;   // even (npad % 256 == 0)

    // lane-constant word index into sbf for this warp (kk adds 128)
    const int bfbase = w * 256 + lane * 4;

#define PREFETCH(c0, buf)                                                          \
    do {                                                                           \
        CP16(smem_u32(&sv[buf][tid]), &g_yp[(c0) * CHUNK + tid]);                  \
        CP16(smem_u32(&sbf[buf][tid * 4]), &g_bf[(c0) * 1024 + tid * 4]);          \
        CP16(smem_u32(&sbf[buf][512 + tid * 4]),                                   \
             &g_bf[(c0) * 1024 + 512 + tid * 4]);                                  \
        asm volatile("cp.async.commit_group;" ::: "memory");                       \
    } while (0)

#define DO_CHUNK(buf)                                                              \
    do {                                                                           \
        _Pragma("unroll")                                                          \
        for (int kk = 0; kk < 2; ++kk) {                                           \
            const int pp = w * 16 + kk * 8 + t4;   /* j-pair index in chunk */     \
            ulonglong2 va0 = sv[buf][2 * pp];                                      \
            ulonglong2 vb0 = sv[buf][2 * pp + 1];                                  \
            ulonglong2 va1 = sv[buf][2 * (pp + 4)];                                \
            ulonglong2 vb1 = sv[buf][2 * (pp + 4) + 1];                            \
            uint4 bb = *reinterpret_cast<const uint4*>(                            \
                &sbf[buf][bfbase + kk * 128]);                                     \
            _Pragma("unroll")                                                      \
            for (int rt = 0; rt < 2; ++rt) {                                       \
                uint32_t ah[4];                                                    \
                ah[0] = phi2pack(Xd[2 * rt],     va0, vb0);                        \
                ah[1] = phi2pack(Xd[2 * rt + 1], va0, vb0);                        \
                ah[2] = phi2pack(Xd[2 * rt],     va1, vb1);                        \
                ah[3] = phi2pack(Xd[2 * rt + 1], va1, vb1);                        \
                mma_f16(acc[rt][0], ah, bb.x, bb.y);                               \
                mma_f16(acc[rt][1], ah, bb.z, bb.w);                               \
            }                                                                      \
        }                                                                          \
    } while (0)

    PREFETCH(0, 0);
    PREFETCH(1, 1);

    for (int t = 0; t < nchunks; t += 2) {
        asm volatile("cp.async.wait_group 1;" ::: "memory");
        __syncthreads();
        DO_CHUNK(0);
        __syncthreads();
        if (t + 2 < nchunks) PREFETCH(t + 2, 0);
        else asm volatile("cp.async.commit_group;" ::: "memory");

        asm volatile("cp.async.wait_group 1;" ::: "memory");
        __syncthreads();
        DO_CHUNK(1);
        __syncthreads();
        if (t + 3 < nchunks) PREFETCH(t + 3, 1);
        else asm volatile("cp.async.commit_group;" ::: "memory");
    }
    asm volatile("cp.async.wait_group 0;" ::: "memory");

    // ---- 4-way j combine: warps 1-3 publish, warp 0 reduces ----
    if (w > 0) {
#pragma unroll
        for (int rt = 0; rt < 2; ++rt)
#pragma unroll
            for (int nt = 0; nt < 2; ++nt)
#pragma unroll
                for (int q = 0; q < 4; ++q)
                    sred[w - 1][lane][rt * 8 + nt * 4 + q] = acc[rt][nt][q];
    }
    __syncthreads();
    if (w > 0) return;

#pragma unroll
    for (int ww = 0; ww < 3; ++ww)
#pragma unroll
        for (int rt = 0; rt < 2; ++rt)
#pragma unroll
            for (int nt = 0; nt < 2; ++nt)
#pragma unroll
                for (int q = 0; q < 4; ++q)
                    acc[rt][nt][q] += sred[ww][lane][rt * 8 + nt * 4 + q];

    // ---- epilogue: polynomial part (unscaled coeffs) + store ----
    const float sh0 = __ldg(&shift[0]), sh1 = __ldg(&shift[1]), sh2 = __ldg(&shift[2]);
    const float sl0 = __ldg(&scale[0]), sl1 = __ldg(&scale[1]), sl2 = __ldg(&scale[2]);

#pragma unroll
    for (int i = 0; i < 4; ++i) {
        int grow = tilebase + g + 8 * i;
        if (grow >= nx) continue;
        float xcx = unpk(Xd[i].x).x;
        float xcy = unpk(Xd[i].y).x;
        float xcz = unpk(Xd[i].z).x;
        float xh0 = (xcx - sh0) / sl0;
        float xh1 = (xcy - sh1) / sl1;
        float xh2 = (xcz - sh2) / sl2;
        const int rt = i >> 1, up = i & 1;

#pragma unroll
        for (int nt = 0; nt < 2; ++nt) {
            const int col = 2 * t4 + 8 * nt;
            float o0 = acc[rt][nt][up * 2 + 0];
            float o1 = acc[rt][nt][up * 2 + 1];
            for (int k = 0; k < r; ++k) {
                float p = 1.f;
                int e0 = __ldg(&powers[k * 3 + 0]);
                int e1 = __ldg(&powers[k * 3 + 1]);
                int e2 = __ldg(&powers[k * 3 + 2]);
                for (int q = 0; q < e0; ++q) p *= xh0;
                for (int q = 0; q < e1; ++q) p *= xh1;
                for (int q = 0; q < e2; ++q) p *= xh2;
                float cc0 = __ldg(&coeffs[(size_t)(n + k) * MM + col]);
                float cc1 = __ldg(&coeffs[(size_t)(n + k) * MM + col + 1]);
                o0 = fmaf(p, cc0, o0);
                o1 = fmaf(p, cc1, o1);
            }
            *reinterpret_cast<float2*>(&out[(size_t)grow * MM + col]) = make_float2(o0, o1);
        }
    }
}

extern "C" void kernel_launch(void* const* d_in, const int* in_sizes, int n_in,
                              void* d_out, int out_size) {
    const float* x      = (const float*)d_in[0];
    const float* y      = (const float*)d_in[1];
    const float* shift  = (const float*)d_in[2];
    const float* scale  = (const float*)d_in[3];
    const float* coeffs = (const float*)d_in[4];
    const int*   powers = (const int*)d_in[5];

    int nx = in_sizes[0] / 3;
    int n  = in_sizes[1] / 3;
    int r  = in_sizes[5] / 3;

    int npad = (n + 255) & ~255;     // even number of 128-chunks
    if (npad > NMAX) npad = NMAX;

    int prep_work = (npad >> 4) * 128;
    int npairs = npad >> 1;
    if (npairs > prep_work) prep_work = npairs;
    prep_kernel<<<(prep_work + 255) / 256, 256>>>(y, coeffs, n, npad);

    int grid = (nx + MTILE - 1) / MTILE;
    rbf_tps_mma_kernel<<<grid, BLOCK>>>(x, shift, scale, coeffs, powers,
                                        (float*)d_out, nx, n, npad, r);
}

// round 17
// speedup vs baseline: 1.0600x; 1.0600x over previous
#include <cuda_runtime.h>
#include <cstdint>

#define BLOCK 128
#define MTILE 32
#define MM 16
#define NMAX 8192
#define CHUNK 256
#define HALF_LN2 0.34657359027997264f
#define EPS_S 1e-5f

typedef unsigned long long ull;

// prologue-packed operands
// g_yp: per j-pair p (j0=2p, j1=2p+1): [2p]   = (x0, x1, y0, y1)
//                                      [2p+1] = (z0, z1, w0+eps, w1+eps)  (w=|y|^2)
__device__ float4 g_yp[NMAX];
// g_bf: fragment-major B. Per 8-pair block gb, lane l (t4=l&3, g=l>>2), word w:
//   w0=(pair t4,  col g) w1=(pair t4+4, col g) w2=(pair t4, col g+8) w3=(pair t4+4, col g+8)
//   each word = f16x2(0.5*ln2*coeff[2p][c], 0.5*ln2*coeff[2p+1][c])
__device__ uint32_t g_bf[(NMAX / 16) * 128];

__device__ __forceinline__ uint32_t pack_f16x2(float lo, float hi) {
    uint32_t d;
    asm("cvt.rn.f16x2.f32 %0, %1, %2;" : "=r"(d) : "f"(hi), "f"(lo));
    return d;
}

// ---- packed f32x2 helpers (Blackwell FFMA2 path) ----
__device__ __forceinline__ ull fma2(ull a, ull b, ull c) {
    ull d;
    asm("fma.rn.f32x2 %0, %1, %2, %3;" : "=l"(d) : "l"(a), "l"(b), "l"(c));
    return d;
}
__device__ __forceinline__ ull add2(ull a, ull b) {
    ull d;
    asm("add.rn.f32x2 %0, %1, %2;" : "=l"(d) : "l"(a), "l"(b));
    return d;
}
__device__ __forceinline__ ull dup2(float v) {
    ull d;
    uint32_t b = __float_as_uint(v);
    asm("mov.b64 %0, {%1, %2};" : "=l"(d) : "r"(b), "r"(b));
    return d;
}
__device__ __forceinline__ float2 unpk(ull p) {
    uint32_t lo, hi;
    asm("mov.b64 {%0, %1}, %2;" : "=r"(lo), "=r"(hi) : "l"(p));
    return make_float2(__uint_as_float(lo), __uint_as_float(hi));
}

struct XP { ull x, y, z, w; };   // duplicated (v,v) per component; w = |x|^2

// phi for a j-pair against one x row, returned as f16x2 A-fragment word.
// s = |x|^2 + (-2x.y) + |y|^2+eps > 0 guaranteed (eps dominates fp32 rounding).
// Tree-form dot: depth 3 instead of 4.
__device__ __forceinline__ uint32_t phi2pack(const XP& X, ulonglong2 a, ulonglong2 b) {
    ull u = fma2(X.x, a.x, b.y);     // x0*(-2y0) + (|y|^2+eps)
    u = fma2(X.y, a.y, u);
    ull v = fma2(X.z, b.x, X.w);     // x2*(-2y2) + |x|^2
    ull s = add2(u, v);
    float2 sf = unpk(s);
    float p0 = sf.x * __log2f(sf.x);
    float p1 = sf.y * __log2f(sf.y);
    return pack_f16x2(p0, p1);
}

__device__ __forceinline__ void mma_f16(float* c, const uint32_t* a, uint32_t b0, uint32_t b1) {
    asm volatile(
        "mma.sync.aligned.m16n8k16.row.col.f32.f16.f16.f32 "
        "{%0,%1,%2,%3}, {%4,%5,%6,%7}, {%8,%9}, {%0,%1,%2,%3};"
        : "+f"(c[0]), "+f"(c[1]), "+f"(c[2]), "+f"(c[3])
        : "r"(a[0]), "r"(a[1]), "r"(a[2]), "r"(a[3]), "r"(b0), "r"(b1));
}

__device__ __forceinline__ uint32_t smem_u32(const void* p) {
    uint32_t a;
    asm("{ .reg .u64 t; cvta.to.shared.u64 t, %1; cvt.u32.u64 %0, t; }" : "=r"(a) : "l"(p));
    return a;
}

#define CP16(dst_u32, src_ptr) \
    asm volatile("cp.async.cg.shared.global [%0], [%1], 16;" :: "r"(dst_u32), "l"(src_ptr))

// ---------------- prologue ----------------
__global__ void prep_kernel(const float* __restrict__ y,
                            const float* __restrict__ coeffs,
                            int n, int npad) {
    int i = blockIdx.x * blockDim.x + threadIdx.x;
    int npairs = npad >> 1;
    if (i < npairs) {
        int j0 = 2 * i, j1 = 2 * i + 1;
        float a0 = 0.f, b0 = 0.f, c0 = 0.f, w0 = 1.f;
        float a1 = 0.f, b1 = 0.f, c1 = 0.f, w1 = 1.f;
        if (j0 < n) {
            a0 = y[3 * j0]; b0 = y[3 * j0 + 1]; c0 = y[3 * j0 + 2];
            w0 = fmaf(a0, a0, fmaf(b0, b0, c0 * c0)) + EPS_S;
            a0 = -2.f * a0; b0 = -2.f * b0; c0 = -2.f * c0;
        }
        if (j1 < n) {
            a1 = y[3 * j1]; b1 = y[3 * j1 + 1]; c1 = y[3 * j1 + 2];
            w1 = fmaf(a1, a1, fmaf(b1, b1, c1 * c1)) + EPS_S;
            a1 = -2.f * a1; b1 = -2.f * b1; c1 = -2.f * c1;
        }
        g_yp[2 * i + 0] = make_float4(a0, a1, b0, b1);
        g_yp[2 * i + 1] = make_float4(c0, c1, w0, w1);
    }
    // fragment-major B: i over (npad/16 blocks) * 128 words
    int npe = (npad >> 4) * 128;
    if (i < npe) {
        int gb = i >> 7;            // 8-pair block
        int l  = (i >> 2) & 31;     // lane
        int wd = i & 3;             // word
        int t4 = l & 3, g = l >> 2;
        int pl  = t4 + (wd & 1) * 4;        // pair within block
        int col = g + (wd >> 1) * 8;        // output column
        int p   = gb * 8 + pl;              // global pair
        int j0 = 2 * p, j1 = 2 * p + 1;
        float f0 = (j0 < n) ? HALF_LN2 * coeffs[(size_t)j0 * MM + col] : 0.f;
        float f1 = (j1 < n) ? HALF_LN2 * coeffs[(size_t)j1 * MM + col] : 0.f;
        g_bf[i] = pack_f16x2(f0, f1);
    }
}

// ---------------- main kernel ----------------
__global__ __launch_bounds__(BLOCK, 5) void rbf_tps_mma_kernel(
    const float* __restrict__ x,
    const float* __restrict__ shift,
    const float* __restrict__ scale,
    const float* __restrict__ coeffs,
    const int*   __restrict__ powers,
    float* __restrict__ out,
    int nx, int n, int npad, int r)
{
    __shared__ __align__(16) ulonglong2 sv[2][CHUNK];   // 8 KB: 128 pairs x 2 entries per buf
    __shared__ __align__(16) uint32_t sbf[2][2048];     // 16 KB fragment-major B
    __shared__ float sred[3][32][MM];                   // 6 KB

    const int tid  = threadIdx.x;
    const int lane = tid & 31;
    const int w    = tid >> 5;
    const int t4   = lane & 3;
    const int g    = lane >> 2;

    const int tilebase = blockIdx.x * MTILE;

    // duplicated x operands for rows g, g+8, g+16, g+24
    XP Xd[4];
#pragma unroll
    for (int i = 0; i < 4; ++i) {
        int row = tilebase + g + 8 * i;
        float xx = 0.f, xy = 0.f, xz = 0.f;
        if (row < nx) {
            xx = x[3 * row + 0];
            xy = x[3 * row + 1];
            xz = x[3 * row + 2];
        }
        float x2 = fmaf(xx, xx, fmaf(xy, xy, xz * xz));
        Xd[i].x = dup2(xx);
        Xd[i].y = dup2(xy);
        Xd[i].z = dup2(xz);
        Xd[i].w = dup2(x2);
    }

    float acc[2][2][4];
#pragma unroll
    for (int a = 0; a < 2; ++a)
#pragma unroll
        for (int b = 0; b < 2; ++b)
#pragma unroll
            for (int c = 0; c < 4; ++c) acc[a][b][c] = 0.f;

    const int nchunks = npad / CHUNK;   // even (npad % 512 == 0)

    // lane-constant word index into sbf for this warp (kk adds 128)
    const int bfbase = w * 512 + lane * 4;

// One chunk of 256 j = 128 pairs = CHUNK float4 entries of g_yp and 2048 B words.
#define PREFETCH(c0, buf)                                                          \
    do {                                                                           \
        CP16(smem_u32(&sv[buf][tid]), &g_yp[(c0) * CHUNK + tid]);                  \
        CP16(smem_u32(&sv[buf][tid + 128]), &g_yp[(c0) * CHUNK + tid + 128]);      \
        _Pragma("unroll")                                                          \
        for (int q = 0; q < 4; ++q)                                                \
            CP16(smem_u32(&sbf[buf][tid * 4 + q * 512]),                           \
                 &g_bf[(c0) * 2048 + tid * 4 + q * 512]);                          \
        asm volatile("cp.async.commit_group;" ::: "memory");                       \
    } while (0)

#define DO_CHUNK(buf)                                                              \
    do {                                                                           \
        _Pragma("unroll")                                                          \
        for (int kk = 0; kk < 4; ++kk) {                                           \
            const int pp = w * 32 + kk * 8 + t4;   /* j-pair index in chunk */     \
            ulonglong2 va0 = sv[buf][2 * pp];                                      \
            ulonglong2 vb0 = sv[buf][2 * pp + 1];                                  \
            ulonglong2 va1 = sv[buf][2 * (pp + 4)];                                \
            ulonglong2 vb1 = sv[buf][2 * (pp + 4) + 1];                            \
            uint4 bb = *reinterpret_cast<const uint4*>(                            \
                &sbf[buf][bfbase + kk * 128]);                                     \
            _Pragma("unroll")                                                      \
            for (int rt = 0; rt < 2; ++rt) {                                       \
                uint32_t ah[4];                                                    \
                ah[0] = phi2pack(Xd[2 * rt],     va0, vb0);                        \
                ah[1] = phi2pack(Xd[2 * rt + 1], va0, vb0);                        \
                ah[2] = phi2pack(Xd[2 * rt],     va1, vb1);                        \
                ah[3] = phi2pack(Xd[2 * rt + 1], va1, vb1);                        \
                mma_f16(acc[rt][0], ah, bb.x, bb.y);                               \
                mma_f16(acc[rt][1], ah, bb.z, bb.w);                               \
            }                                                                      \
        }                                                                          \
    } while (0)

    PREFETCH(0, 0);
    PREFETCH(1, 1);

    for (int t = 0; t < nchunks; t += 2) {
        asm volatile("cp.async.wait_group 1;" ::: "memory");
        __syncthreads();
        DO_CHUNK(0);
        __syncthreads();
        if (t + 2 < nchunks) PREFETCH(t + 2, 0);
        else asm volatile("cp.async.commit_group;" ::: "memory");

        asm volatile("cp.async.wait_group 1;" ::: "memory");
        __syncthreads();
        DO_CHUNK(1);
        __syncthreads();
        if (t + 3 < nchunks) PREFETCH(t + 3, 1);
        else asm volatile("cp.async.commit_group;" ::: "memory");
    }
    asm volatile("cp.async.wait_group 0;" ::: "memory");

    // ---- 4-way j combine: warps 1-3 publish, warp 0 reduces ----
    if (w > 0) {
#pragma unroll
        for (int rt = 0; rt < 2; ++rt)
#pragma unroll
            for (int nt = 0; nt < 2; ++nt)
#pragma unroll
                for (int q = 0; q < 4; ++q)
                    sred[w - 1][lane][rt * 8 + nt * 4 + q] = acc[rt][nt][q];
    }
    __syncthreads();
    if (w > 0) return;

#pragma unroll
    for (int ww = 0; ww < 3; ++ww)
#pragma unroll
        for (int rt = 0; rt < 2; ++rt)
#pragma unroll
            for (int nt = 0; nt < 2; ++nt)
#pragma unroll
                for (int q = 0; q < 4; ++q)
                    acc[rt][nt][q] += sred[ww][lane][rt * 8 + nt * 4 + q];

    // ---- epilogue: polynomial part (unscaled coeffs) + store ----
    const float sh0 = __ldg(&shift[0]), sh1 = __ldg(&shift[1]), sh2 = __ldg(&shift[2]);
    const float sl0 = __ldg(&scale[0]), sl1 = __ldg(&scale[1]), sl2 = __ldg(&scale[2]);

#pragma unroll
    for (int i = 0; i < 4; ++i) {
        int grow = tilebase + g + 8 * i;
        if (grow >= nx) continue;
        float xcx = unpk(Xd[i].x).x;
        float xcy = unpk(Xd[i].y).x;
        float xcz = unpk(Xd[i].z).x;
        float xh0 = (xcx - sh0) / sl0;
        float xh1 = (xcy - sh1) / sl1;
        float xh2 = (xcz - sh2) / sl2;
        const int rt = i >> 1, up = i & 1;

#pragma unroll
        for (int nt = 0; nt < 2; ++nt) {
            const int col = 2 * t4 + 8 * nt;
            float o0 = acc[rt][nt][up * 2 + 0];
            float o1 = acc[rt][nt][up * 2 + 1];
            for (int k = 0; k < r; ++k) {
                float p = 1.f;
                int e0 = __ldg(&powers[k * 3 + 0]);
                int e1 = __ldg(&powers[k * 3 + 1]);
                int e2 = __ldg(&powers[k * 3 + 2]);
                for (int q = 0; q < e0; ++q) p *= xh0;
                for (int q = 0; q < e1; ++q) p *= xh1;
                for (int q = 0; q < e2; ++q) p *= xh2;
                float cc0 = __ldg(&coeffs[(size_t)(n + k) * MM + col]);
                float cc1 = __ldg(&coeffs[(size_t)(n + k) * MM + col + 1]);
                o0 = fmaf(p, cc0, o0);
                o1 = fmaf(p, cc1, o1);
            }
            *reinterpret_cast<float2*>(&out[(size_t)grow * MM + col]) = make_float2(o0, o1);
        }
    }
}

extern "C" void kernel_launch(void* const* d_in, const int* in_sizes, int n_in,
                              void* d_out, int out_size) {
    const float* x      = (const float*)d_in[0];
    const float* y      = (const float*)d_in[1];
    const float* shift  = (const float*)d_in[2];
    const float* scale  = (const float*)d_in[3];
    const float* coeffs = (const float*)d_in[4];
    const int*   powers = (const int*)d_in[5];

    int nx = in_sizes[0] / 3;
    int n  = in_sizes[1] / 3;
    int r  = in_sizes[5] / 3;

    int npad = (n + 511) & ~511;     // even number of 256-chunks
    if (npad > NMAX) npad = NMAX;

    int prep_work = (npad >> 4) * 128;
    int npairs = npad >> 1;
    if (npairs > prep_work) prep_work = npairs;
    prep_kernel<<<(prep_work + 255) / 256, 256>>>(y, coeffs, n, npad);

    int grid = (nx + MTILE - 1) / MTILE;
    rbf_tps_mma_kernel<<<grid, BLOCK>>>(x, shift, scale, coeffs, powers,
                                        (float*)d_out, nx, n, npad, r);
}